// round 17
// baseline (speedup 1.0000x reference)
#include <cuda_runtime.h>
#include <cstdint>

#define NN    4096
#define IND   256
#define EDIM  16
#define NAF   16
#define LATD  128
#define NBT   5
#define EMAX  262144

#define LAT_OFF   0
#define ATOM_OFF  (NN * LATD)              // 524288
#define BOND_OFF  (NN * LATD + NN * NAF)   // 589824

__device__ float g_s1[NN * IND];           // 4 MB
__device__ int   g_map[NN * NN];           // 64 MB: (j,i) -> winning edge k+1 (zero-invariant)

// ---------- packed f32x2 helpers ----------
static __device__ __forceinline__ unsigned long long pk2(float lo, float hi) {
    unsigned long long r;
    asm("mov.b64 %0, {%1, %2};" : "=l"(r) : "f"(lo), "f"(hi));
    return r;
}
static __device__ __forceinline__ unsigned long long dup2(float v) {
    unsigned long long r;
    asm("mov.b64 %0, {%1, %1};" : "=l"(r) : "f"(v));
    return r;
}
static __device__ __forceinline__ void up2(float &lo, float &hi, unsigned long long v) {
    asm("mov.b64 {%0, %1}, %2;" : "=f"(lo), "=f"(hi) : "l"(v));
}
static __device__ __forceinline__ void fma2(unsigned long long &d,
                                            unsigned long long a,
                                            unsigned long long b) {
    asm("fma.rn.f32x2 %0, %1, %2, %0;" : "+l"(d) : "l"(a), "l"(b));
}
static __device__ __forceinline__ unsigned long long add2(unsigned long long a,
                                                          unsigned long long b) {
    unsigned long long r;
    asm("add.rn.f32x2 %0, %1, %2;" : "=l"(r) : "l"(a), "l"(b));
    return r;
}
static __device__ __forceinline__ float silu_f(float x) {
    return __fdividef(x, 1.0f + __expf(-x));
}

// ---------- K1: s1 = silu(s @ W_sharedᵀ + b_shared) ----------
__global__ __launch_bounds__(256) void k_gemm_silu(
    const float* __restrict__ A, const float* __restrict__ W,
    const float* __restrict__ bias)
{
    __shared__ float As[32][132];
    __shared__ float Bs[32][68];
    const int tid = threadIdx.x;
    const int bm = blockIdx.y * 128, bn = blockIdx.x * 64;
    const int tx = tid & 15, ty = tid >> 4;

    float acc[8][4];
    #pragma unroll
    for (int i = 0; i < 8; i++)
        #pragma unroll
        for (int j = 0; j < 4; j++) acc[i][j] = 0.f;

    for (int kk = 0; kk < 256; kk += 32) {
        #pragma unroll
        for (int l = 0; l < 4; l++) {
            int idx = tid + l * 256;
            int m = idx >> 3, kg = idx & 7;
            float4 v = *(const float4*)&A[(bm + m) * 256 + kk + kg * 4];
            As[kg * 4 + 0][m] = v.x; As[kg * 4 + 1][m] = v.y;
            As[kg * 4 + 2][m] = v.z; As[kg * 4 + 3][m] = v.w;
        }
        #pragma unroll
        for (int l = 0; l < 2; l++) {
            int idx = tid + l * 256;
            int c = idx >> 3, kg = idx & 7;
            float4 v = *(const float4*)&W[(bn + c) * 256 + kk + kg * 4];
            Bs[kg * 4 + 0][c] = v.x; Bs[kg * 4 + 1][c] = v.y;
            Bs[kg * 4 + 2][c] = v.z; Bs[kg * 4 + 3][c] = v.w;
        }
        __syncthreads();
        #pragma unroll
        for (int k = 0; k < 32; k++) {
            float4 a0 = *(const float4*)&As[k][ty * 8];
            float4 a1 = *(const float4*)&As[k][ty * 8 + 4];
            float4 b  = *(const float4*)&Bs[k][tx * 4];
            float aa[8] = {a0.x, a0.y, a0.z, a0.w, a1.x, a1.y, a1.z, a1.w};
            float bb[4] = {b.x, b.y, b.z, b.w};
            #pragma unroll
            for (int i = 0; i < 8; i++)
                #pragma unroll
                for (int j = 0; j < 4; j++)
                    acc[i][j] = fmaf(aa[i], bb[j], acc[i][j]);
        }
        __syncthreads();
    }
    float4 b4 = *(const float4*)&bias[bn + tx * 4];
    const float bv[4] = {b4.x, b4.y, b4.z, b4.w};
    #pragma unroll
    for (int i = 0; i < 8; i++) {
        int row = bm + ty * 8 + i;
        float4 o;
        o.x = silu_f(acc[i][0] + bv[0]);
        o.y = silu_f(acc[i][1] + bv[1]);
        o.z = silu_f(acc[i][2] + bv[2]);
        o.w = silu_f(acc[i][3] + bv[3]);
        *(float4*)&g_s1[row * 256 + bn + tx * 4] = o;
    }
}

// ---------- K2: atoms_out = s1 @ W_atomsᵀ + b_atoms ----------
__global__ __launch_bounds__(256) void k_gemm_atoms(
    const float* __restrict__ W, const float* __restrict__ bias,
    float* __restrict__ out)
{
    __shared__ float As[32][132];
    __shared__ float Bs[32][52];
    const int tid = threadIdx.x;
    const int bm = blockIdx.y * 128, bn = blockIdx.x * 48;
    const int tx = tid & 15, ty = tid >> 4;

    float acc[8][3];
    #pragma unroll
    for (int i = 0; i < 8; i++)
        #pragma unroll
        for (int j = 0; j < 3; j++) acc[i][j] = 0.f;

    for (int kk = 0; kk < 256; kk += 32) {
        #pragma unroll
        for (int l = 0; l < 4; l++) {
            int idx = tid + l * 256;
            int m = idx >> 3, kg = idx & 7;
            float4 v = *(const float4*)&g_s1[(bm + m) * 256 + kk + kg * 4];
            As[kg * 4 + 0][m] = v.x; As[kg * 4 + 1][m] = v.y;
            As[kg * 4 + 2][m] = v.z; As[kg * 4 + 3][m] = v.w;
        }
        #pragma unroll
        for (int l = 0; l < 2; l++) {
            int idx = tid + l * 256;
            if (idx < 384) {
                int c = idx >> 3, kg = idx & 7;
                float4 v = *(const float4*)&W[(bn + c) * 256 + kk + kg * 4];
                Bs[kg * 4 + 0][c] = v.x; Bs[kg * 4 + 1][c] = v.y;
                Bs[kg * 4 + 2][c] = v.z; Bs[kg * 4 + 3][c] = v.w;
            }
        }
        __syncthreads();
        #pragma unroll
        for (int k = 0; k < 32; k++) {
            float4 a0 = *(const float4*)&As[k][ty * 8];
            float4 a1 = *(const float4*)&As[k][ty * 8 + 4];
            float aa[8] = {a0.x, a0.y, a0.z, a0.w, a1.x, a1.y, a1.z, a1.w};
            float b0 = Bs[k][tx * 3 + 0];
            float b1 = Bs[k][tx * 3 + 1];
            float b2 = Bs[k][tx * 3 + 2];
            #pragma unroll
            for (int i = 0; i < 8; i++) {
                acc[i][0] = fmaf(aa[i], b0, acc[i][0]);
                acc[i][1] = fmaf(aa[i], b1, acc[i][1]);
                acc[i][2] = fmaf(aa[i], b2, acc[i][2]);
            }
        }
        __syncthreads();
    }
    #pragma unroll
    for (int i = 0; i < 8; i++) {
        int row = bm + ty * 8 + i;
        #pragma unroll
        for (int j = 0; j < 3; j++) {
            int col = bn + tx * 3 + j;
            if (col < NAF + LATD) {
                float val = acc[i][j] + bias[col];
                if (col < NAF)
                    out[ATOM_OFF + row * NAF + col] = val;
                else
                    out[LAT_OFF + row * LATD + (col - NAF)] = val;
            }
        }
    }
}

// ---------- K3: scatter last-write-wins map ----------
__global__ void k_scatter(const int* __restrict__ ei, int E)
{
    int k = blockIdx.x * blockDim.x + threadIdx.x;
    if (k >= E) return;
    int j = ei[k]     & (NN - 1);
    int i = ei[E + k] & (NN - 1);
    atomicMax(&g_map[j * NN + i], k + 1);
}

// ---------- K5: restore g_map zero-invariant (runs AFTER k_edge) ----------
__global__ void k_clear(const int* __restrict__ ei, int E)
{
    int k = blockIdx.x * blockDim.x + threadIdx.x;
    if (k >= E) return;
    int j = ei[k]     & (NN - 1);
    int i = ei[E + k] & (NN - 1);
    g_map[j * NN + i] = 0;
}

// ---------- K6: fused symmetrize + edge MLP + bond head ----------
// 512 blocks x 2 tiles of 256 edges: single wave at ~5 blocks/SM, weights staged once.
// Staging computes e_sym on the fly from g_map + e (replaces the old k_esym kernel).
__global__ __launch_bounds__(256) void k_edge(
    const int* __restrict__ ei,
    const float* __restrict__ e,       // [E][16]
    const float* __restrict__ Wbond,   // [256][16]
    const float* __restrict__ bbond,   // [256]
    const float* __restrict__ Wbonds,  // [5][256]
    const float* __restrict__ bbonds,  // [5]
    float* __restrict__ out, int E)
{
    __shared__ float sWt[16][256];   // W_bondᵀ
    __shared__ float sEs[16][256];   // e_sym tile transposed
    __shared__ float sWb[5][256];
    __shared__ float sBias[256];
    __shared__ float sBb[8];
    __shared__ int   sI[256], sJ[256];

    const int tid = threadIdx.x;

    // Stage weights once per block
    #pragma unroll
    for (int l = 0; l < 16; l++) {
        int idx = tid + l * 256;
        sWt[idx & 15][idx >> 4] = Wbond[idx];
    }
    #pragma unroll
    for (int l = 0; l < 5; l++) sWb[l][tid] = Wbonds[l * 256 + tid];
    sBias[tid] = bbond[tid];
    if (tid < 5) sBb[tid] = bbonds[tid];
    __syncthreads();

    const int lane = tid & 31, wid = tid >> 5;
    const int c0 = lane * 8;

    unsigned long long bias2[4];
    {
        float4 b0 = *(const float4*)&sBias[c0];
        float4 b1 = *(const float4*)&sBias[c0 + 4];
        bias2[0] = pk2(b0.x, b0.y); bias2[1] = pk2(b0.z, b0.w);
        bias2[2] = pk2(b1.x, b1.y); bias2[3] = pk2(b1.z, b1.w);
    }
    const float bb0 = sBb[0], bb1 = sBb[1], bb2 = sBb[2], bb3 = sBb[3], bb4 = sBb[4];

    for (int t = 0; t < 2; t++) {
        const int eb = (blockIdx.x * 2 + t) * 256;

        // ---- Fused esym staging: map lookups + e gathers + symmetrize ----
        {
            int ke = eb + tid;
            if (ke < E) {
                int j = ei[ke]     & (NN - 1);
                int i = ei[E + ke] & (NN - 1);
                sJ[tid] = j; sI[tid] = i;
                int wf = g_map[j * NN + i] - 1;   // >= 0: some edge with this (j,i) wrote it
                int wr = g_map[i * NN + j];       // 0 if no reverse edge
                const float4* pf = (const float4*)(e + (size_t)wf * 16);
                float4 a0 = pf[0], a1 = pf[1], a2 = pf[2], a3 = pf[3];
                if (wr > 0) {
                    const float4* pr = (const float4*)(e + (size_t)(wr - 1) * 16);
                    float4 r0 = pr[0], r1 = pr[1], r2 = pr[2], r3 = pr[3];
                    a0.x += r0.x; a0.y += r0.y; a0.z += r0.z; a0.w += r0.w;
                    a1.x += r1.x; a1.y += r1.y; a1.z += r1.z; a1.w += r1.w;
                    a2.x += r2.x; a2.y += r2.y; a2.z += r2.z; a2.w += r2.w;
                    a3.x += r3.x; a3.y += r3.y; a3.z += r3.z; a3.w += r3.w;
                }
                sEs[ 0][tid] = a0.x * 0.5f; sEs[ 1][tid] = a0.y * 0.5f;
                sEs[ 2][tid] = a0.z * 0.5f; sEs[ 3][tid] = a0.w * 0.5f;
                sEs[ 4][tid] = a1.x * 0.5f; sEs[ 5][tid] = a1.y * 0.5f;
                sEs[ 6][tid] = a1.z * 0.5f; sEs[ 7][tid] = a1.w * 0.5f;
                sEs[ 8][tid] = a2.x * 0.5f; sEs[ 9][tid] = a2.y * 0.5f;
                sEs[10][tid] = a2.z * 0.5f; sEs[11][tid] = a2.w * 0.5f;
                sEs[12][tid] = a3.x * 0.5f; sEs[13][tid] = a3.y * 0.5f;
                sEs[14][tid] = a3.z * 0.5f; sEs[15][tid] = a3.w * 0.5f;
            } else {
                sJ[tid] = 0; sI[tid] = 0;
                #pragma unroll
                for (int d = 0; d < 16; d++) sEs[d][tid] = 0.f;
            }
        }
        __syncthreads();

        for (int it = 0; it < 8; it++) {
            const int e0 = wid * 32 + it * 4;

            // 1) s1 gathers issued early
            ulonglong2 si[4][2], sj[4][2];
            #pragma unroll
            for (int q = 0; q < 4; q++) {
                int gi = sI[e0 + q], gj = sJ[e0 + q];
                const ulonglong2* pi = (const ulonglong2*)(g_s1 + (size_t)gi * 256 + c0);
                const ulonglong2* pj = (const ulonglong2*)(g_s1 + (size_t)gj * 256 + c0);
                si[q][0] = pi[0]; si[q][1] = pi[1];
                sj[q][0] = pj[0]; sj[q][1] = pj[1];
            }

            // 2) matvec (packed f32x2)
            unsigned long long g2[4][4];
            #pragma unroll
            for (int q = 0; q < 4; q++) {
                g2[q][0] = bias2[0]; g2[q][1] = bias2[1];
                g2[q][2] = bias2[2]; g2[q][3] = bias2[3];
            }
            #pragma unroll
            for (int k = 0; k < 16; k++) {
                float4 w0 = *(const float4*)&sWt[k][c0];
                float4 w1 = *(const float4*)&sWt[k][c0 + 4];
                unsigned long long B0 = pk2(w0.x, w0.y), B1 = pk2(w0.z, w0.w);
                unsigned long long B2 = pk2(w1.x, w1.y), B3 = pk2(w1.z, w1.w);
                float4 av = *(const float4*)&sEs[k][e0];
                float as[4] = {av.x, av.y, av.z, av.w};
                #pragma unroll
                for (int q = 0; q < 4; q++) {
                    unsigned long long A = dup2(as[q]);
                    fma2(g2[q][0], A, B0); fma2(g2[q][1], A, B1);
                    fma2(g2[q][2], A, B2); fma2(g2[q][3], A, B3);
                }
            }

            // 3) add gathers, silu
            #pragma unroll
            for (int q = 0; q < 4; q++) {
                g2[q][0] = add2(g2[q][0], add2(si[q][0].x, sj[q][0].x));
                g2[q][1] = add2(g2[q][1], add2(si[q][0].y, sj[q][0].y));
                g2[q][2] = add2(g2[q][2], add2(si[q][1].x, sj[q][1].x));
                g2[q][3] = add2(g2[q][3], add2(si[q][1].y, sj[q][1].y));
                #pragma unroll
                for (int p = 0; p < 4; p++) {
                    float x0, x1; up2(x0, x1, g2[q][p]);
                    g2[q][p] = pk2(silu_f(x0), silu_f(x1));
                }
            }

            // 4) bond head partials
            unsigned long long bq[4][5];
            #pragma unroll
            for (int q = 0; q < 4; q++)
                #pragma unroll
                for (int b = 0; b < 5; b++) bq[q][b] = 0ull;
            #pragma unroll
            for (int b = 0; b < 5; b++) {
                float4 w0 = *(const float4*)&sWb[b][c0];
                float4 w1 = *(const float4*)&sWb[b][c0 + 4];
                unsigned long long W0 = pk2(w0.x, w0.y), W1 = pk2(w0.z, w0.w);
                unsigned long long W2 = pk2(w1.x, w1.y), W3 = pk2(w1.z, w1.w);
                #pragma unroll
                for (int q = 0; q < 4; q++) {
                    fma2(bq[q][b], g2[q][0], W0);
                    fma2(bq[q][b], g2[q][1], W1);
                    fma2(bq[q][b], g2[q][2], W2);
                    fma2(bq[q][b], g2[q][3], W3);
                }
            }

            // 5) reductions
            float v[4][5];
            #pragma unroll
            for (int q = 0; q < 4; q++)
                #pragma unroll
                for (int b = 0; b < 5; b++) {
                    float lo, hi; up2(lo, hi, bq[q][b]);
                    float tt = lo + hi;
                    tt += __shfl_xor_sync(0xffffffffu, tt, 16);
                    tt += __shfl_xor_sync(0xffffffffu, tt, 8);
                    tt += __shfl_xor_sync(0xffffffffu, tt, 4);
                    tt += __shfl_xor_sync(0xffffffffu, tt, 2);
                    tt += __shfl_xor_sync(0xffffffffu, tt, 1);
                    v[q][b] = tt;
                }

            if (lane == 0 && eb + e0 < E) {
                float* o = out + BOND_OFF + (size_t)(eb + e0) * NBT;
                float4 f0 = make_float4(v[0][0] + bb0, v[0][1] + bb1, v[0][2] + bb2, v[0][3] + bb3);
                float4 f1 = make_float4(v[0][4] + bb4, v[1][0] + bb0, v[1][1] + bb1, v[1][2] + bb2);
                float4 f2 = make_float4(v[1][3] + bb3, v[1][4] + bb4, v[2][0] + bb0, v[2][1] + bb1);
                float4 f3 = make_float4(v[2][2] + bb2, v[2][3] + bb3, v[2][4] + bb4, v[3][0] + bb0);
                float4 f4 = make_float4(v[3][1] + bb1, v[3][2] + bb2, v[3][3] + bb3, v[3][4] + bb4);
                *(float4*)(o +  0) = f0;
                *(float4*)(o +  4) = f1;
                *(float4*)(o +  8) = f2;
                *(float4*)(o + 12) = f3;
                *(float4*)(o + 16) = f4;
            }
        }
        __syncthreads();   // WAR: next tile restages sEs/sI/sJ
    }
}

extern "C" void kernel_launch(void* const* d_in, const int* in_sizes, int n_in,
                              void* d_out, int out_size)
{
    const float* s      = (const float*)d_in[0];
    const float* e      = (const float*)d_in[1];
    const int*   ei     = (const int*)d_in[3];   // int32 (JAX demotes int64)
    const float* Wsh    = (const float*)d_in[4];
    const float* bsh    = (const float*)d_in[5];
    const float* Wbond  = (const float*)d_in[6];
    const float* bbond  = (const float*)d_in[7];
    const float* Wbonds = (const float*)d_in[8];
    const float* bbonds = (const float*)d_in[9];
    const float* Watoms = (const float*)d_in[10];
    const float* batoms = (const float*)d_in[11];
    float* out = (float*)d_out;

    const int E = in_sizes[1] / EDIM;   // 262144

    // Node path
    k_gemm_silu<<<dim3(4, 32), 256>>>(s, Wsh, bsh);
    k_gemm_atoms<<<dim3(3, 32), 256>>>(Watoms, batoms, out);

    // Edge path: scatter map -> fused (symmetrize + MLP + head) -> restore map
    int nb = (E + 255) / 256;
    k_scatter<<<nb, 256>>>(ei, E);
    k_edge<<<(E + 511) / 512, 256>>>(ei, e, Wbond, bbond, Wbonds, bbonds, out, E);
    k_clear<<<nb, 256>>>(ei, E);
}